// round 5
// baseline (speedup 1.0000x reference)
#include <cuda_runtime.h>

#define BB 2
#define NN 262144
#define SS 24
#define TOT (BB*NN)
#define EPSV 1e-4f
#define PAD 257
#define NB (NN/256)          // 1024 blocks per batch-phase

// ---- scratch (no allocation allowed; __device__ globals) ----
__device__ float g_wm[TOT];
__device__ float g_u[TOT];
__device__ float g_v[TOT];
__device__ double g_sums[3];   // [0]=sum|A|, [1]=sum(valid), [2]=sum(diff^2)

// ---------------------------------------------------------------------------
__device__ __forceinline__ float blockReduceSum(float v, float* sh) {
    int lane = threadIdx.x & 31;
    int wid  = threadIdx.x >> 5;
    #pragma unroll
    for (int o = 16; o > 0; o >>= 1) v += __shfl_down_sync(0xffffffffu, v, o);
    if (lane == 0) sh[wid] = v;
    __syncthreads();
    v = (threadIdx.x < 8) ? sh[threadIdx.x] : 0.f;
    if (wid == 0) {
        #pragma unroll
        for (int o = 4; o > 0; o >>= 1) v += __shfl_down_sync(0xffffffffu, v, o);
    }
    return v;
}

__device__ __forceinline__ void load_nbr24(const int* __restrict__ nbr,
                                           long long i, int* nn) {
    const int4* nb4 = (const int4*)(nbr + i * SS);
    #pragma unroll
    for (int k = 0; k < 6; k++) {
        int4 q = nb4[k];
        nn[4*k+0] = q.x; nn[4*k+1] = q.y; nn[4*k+2] = q.z; nn[4*k+3] = q.w;
    }
}

__device__ __forceinline__ void stage25(const float* __restrict__ src,
                                        int node0, float* sh_g, int tid) {
    const float* gBase = src + (long long)node0 * 25;
    #pragma unroll
    for (int k = 0; k < 25; k++) {
        int t = k * 256 + tid;
        sh_g[(t % 25) * PAD + t / 25] = gBase[t];
    }
}

// ---------------------------------------------------------------------------
// Phase A: wm = w*vm ; u += diag + G^T scatter (atomics) ; |A| + valid partials
__device__ void phase_init_scatter(int b, int blk, float* sh_g, float* sh_red,
                                   const float* __restrict__ G,
                                   const float* __restrict__ Ad,
                                   const float* __restrict__ Ao,
                                   const float* __restrict__ w,
                                   const float* __restrict__ vm,
                                   const int* __restrict__ nbr) {
    int tid = threadIdx.x;
    int node0 = b * NN + blk * 256;
    stage25(G, node0, sh_g, tid);
    __syncthreads();

    long long i = node0 + tid;
    int base = b * NN;

    float v   = vm[i];
    float wmv = w[i] * v;
    g_wm[i] = wmv;

    int nn[24];
    load_nbr24(nbr, i, nn);

    atomicAdd(&g_u[i], wmv * sh_g[tid]);                 // diagonal
    #pragma unroll
    for (int j = 0; j < SS; j++) {
        int nb = nn[j];
        if ((unsigned)nb < (unsigned)NN)
            atomicAdd(&g_u[base + nb], wmv * sh_g[(j + 1) * PAD + tid]);
    }

    // flat |A| partial (coalesced float4 over this batch's Ao slab)
    float s = fabsf(Ad[i]);
    const float4* A4 = (const float4*)(Ao + (long long)b * NN * SS);
    int li = blk * 256 + tid;
    #pragma unroll
    for (int k = 0; k < 6; k++) {
        float4 a = A4[(long long)k * NN + li];
        s += fabsf(a.x) + fabsf(a.y) + fabsf(a.z) + fabsf(a.w);
    }
    float ba = blockReduceSum(s, sh_red);
    if (tid == 0) atomicAdd(&g_sums[0], (double)ba);
    __syncthreads();
    float bv = blockReduceSum(v, sh_red);
    if (tid == 0) atomicAdd(&g_sums[1], (double)bv);
}

// Phase B: v = G u + eps*wm
__device__ void phase_gather_v(int b, int blk, float* sh_g,
                               const float* __restrict__ G,
                               const int* __restrict__ nbr) {
    int tid = threadIdx.x;
    int node0 = b * NN + blk * 256;
    stage25(G, node0, sh_g, tid);
    __syncthreads();

    long long i = node0 + tid;
    int base = b * NN;

    int nn[24];
    load_nbr24(nbr, i, nn);
    float xs[24];
    #pragma unroll
    for (int j = 0; j < SS; j++)
        xs[j] = ((unsigned)nn[j] < (unsigned)NN) ? g_u[base + nn[j]] : 0.f;

    float acc = g_u[i] * sh_g[tid];
    #pragma unroll
    for (int j = 0; j < SS; j++)
        acc = fmaf(xs[j], sh_g[(j + 1) * PAD + tid], acc);

    g_v[i] = acc + EPSV * g_wm[i];
}

// Phase C: y = A v ; z = y/norm ; accumulate diff^2
__device__ void phase_gather_y(int b, int blk, float* sh_a, float* sh_red,
                               const float* __restrict__ Ad,
                               const float* __restrict__ Ao,
                               const float* __restrict__ vm,
                               const int* __restrict__ nbr) {
    __shared__ float s_inv;
    int tid = threadIdx.x;
    int node0 = b * NN + blk * 256;

    const float* aBase = Ao + (long long)node0 * SS;
    #pragma unroll
    for (int k = 0; k < 24; k++) {
        int t = k * 256 + tid;
        sh_a[(t % 24) * PAD + t / 24] = aBase[t];
    }
    if (tid == 0) {
        double norm = g_sums[0] / (g_sums[1] * 25.0 + 1e-6);
        s_inv = (float)(1.0 / (norm + 1e-8));
    }
    __syncthreads();

    long long i = node0 + tid;
    int base = b * NN;

    int nn[24];
    load_nbr24(nbr, i, nn);
    float xs[24];
    #pragma unroll
    for (int j = 0; j < SS; j++)
        xs[j] = ((unsigned)nn[j] < (unsigned)NN) ? g_v[base + nn[j]] : 0.f;

    float acc = g_v[i] * Ad[i];
    #pragma unroll
    for (int j = 0; j < SS; j++)
        acc = fmaf(xs[j], sh_a[j * PAD + tid], acc);

    float z = acc * s_inv;
    float d = (z - g_wm[i]) * vm[i];
    float s = blockReduceSum(d * d, sh_red);
    if (tid == 0) atomicAdd(&g_sums[2], (double)s);
}

// ---------------------------------------------------------------------------
__global__ __launch_bounds__(256) void k_zero() {
    long long i = (long long)blockIdx.x * blockDim.x + threadIdx.x;
    if (i == 0) { g_sums[0] = 0.0; g_sums[1] = 0.0; g_sums[2] = 0.0; }
    float4* u4 = (float4*)g_u;
    if (i < TOT / 4) u4[i] = make_float4(0.f, 0.f, 0.f, 0.f);
}

// slot2: init_scatter(b0)
__global__ __launch_bounds__(256) void k_slot2(const float* __restrict__ G,
                                               const float* __restrict__ Ad,
                                               const float* __restrict__ Ao,
                                               const float* __restrict__ w,
                                               const float* __restrict__ vm,
                                               const int* __restrict__ nbr) {
    __shared__ float sh_g[25 * PAD];
    __shared__ float sh_red[8];
    phase_init_scatter(0, blockIdx.x, sh_g, sh_red, G, Ad, Ao, w, vm, nbr);
}

// slot3: init_scatter(b1) [even blocks] || gather_v(b0) [odd blocks]
__global__ __launch_bounds__(256) void k_slot3(const float* __restrict__ G,
                                               const float* __restrict__ Ad,
                                               const float* __restrict__ Ao,
                                               const float* __restrict__ w,
                                               const float* __restrict__ vm,
                                               const int* __restrict__ nbr) {
    __shared__ float sh_g[25 * PAD];
    __shared__ float sh_red[8];
    int sub = blockIdx.x >> 1;
    if ((blockIdx.x & 1) == 0)
        phase_init_scatter(1, sub, sh_g, sh_red, G, Ad, Ao, w, vm, nbr);
    else
        phase_gather_v(0, sub, sh_g, G, nbr);
}

// slot4: gather_v(b1) [even] || gather_y(b0) [odd]
__global__ __launch_bounds__(256) void k_slot4(const float* __restrict__ G,
                                               const float* __restrict__ Ad,
                                               const float* __restrict__ Ao,
                                               const float* __restrict__ vm,
                                               const int* __restrict__ nbr) {
    __shared__ float sh_g[25 * PAD];
    __shared__ float sh_red[8];
    int sub = blockIdx.x >> 1;
    if ((blockIdx.x & 1) == 0)
        phase_gather_v(1, sub, sh_g, G, nbr);
    else
        phase_gather_y(0, sub, sh_g, sh_red, Ad, Ao, vm, nbr);
}

// slot5: gather_y(b1)
__global__ __launch_bounds__(256) void k_slot5(const float* __restrict__ Ad,
                                               const float* __restrict__ Ao,
                                               const float* __restrict__ vm,
                                               const int* __restrict__ nbr) {
    __shared__ float sh_a[25 * PAD];
    __shared__ float sh_red[8];
    phase_gather_y(1, blockIdx.x, sh_a, sh_red, Ad, Ao, vm, nbr);
}

__global__ void k_final(float* out) {
    out[0] = (float)(g_sums[2] / (g_sums[1] + 1e-6));
}

// ---------------------------------------------------------------------------
extern "C" void kernel_launch(void* const* d_in, const int* in_sizes, int n_in,
                              void* d_out, int out_size) {
    const float* G   = (const float*)d_in[0];   // [2,N,25]
    const float* Ad  = (const float*)d_in[1];   // [2,N,1]
    const float* Ao  = (const float*)d_in[2];   // [2,N,24]
    const float* w   = (const float*)d_in[3];   // [2,N,1]
    const float* vm  = (const float*)d_in[4];   // [2,N,1]
    const int*   nbr = (const int*)d_in[5];     // [2,N,24] int32
    float* out = (float*)d_out;

    const int T = 256;
    const int zeroBlocks = TOT / 4 / T;         // 512

    k_zero <<<zeroBlocks, T>>>();
    k_slot2<<<NB,       T>>>(G, Ad, Ao, w, vm, nbr);
    k_slot3<<<2 * NB,   T>>>(G, Ad, Ao, w, vm, nbr);
    k_slot4<<<2 * NB,   T>>>(G, Ad, Ao, vm, nbr);
    k_slot5<<<NB,       T>>>(Ad, Ao, vm, nbr);
    k_final<<<1, 1>>>(out);
}